// round 12
// baseline (speedup 1.0000x reference)
#include <cuda_runtime.h>
#include <cuda_fp16.h>
#include <cstdint>
#include <math.h>

#define T_TOKENS 8192
#define D_DIM    4096
#define NCOLS    192
#define BM       64
#define KT       64
#define NT       (D_DIM / KT)     // 64
#define ASTR     72               // halves per smem row (64 data + 8 pad)

// smem layout in HALVES
#define SZ_A    (BM * ASTR)            // 4608
#define SZ_B    (NCOLS * ASTR)         // 13824
#define OFF_AH  0
#define OFF_AL  (OFF_AH + 2 * SZ_A)    // 9216
#define OFF_BH  (OFF_AL + 2 * SZ_A)    // 18432
#define OFF_BL  (OFF_BH + 2 * SZ_B)    // 46080
#define SM_HALVES (OFF_BL + 2 * SZ_B)  // 73728
#define SM_BYTES  (SM_HALVES * 2)      // 147456

__device__ float4 g_gates[T_TOKENS];
__device__ __half g_whi[NCOLS * D_DIM];   // weights hi, [n][k]
__device__ __half g_wlo[NCOLS * D_DIM];   // weights (lo*2048), [n][k]

// ---------------- helpers ----------------
__device__ __forceinline__ uint32_t smem_u32(const void* p) {
    uint32_t a;
    asm("{ .reg .u64 t; cvta.to.shared.u64 t, %1; cvt.u32.u64 %0, t; }"
        : "=r"(a) : "l"(p));
    return a;
}
__device__ __forceinline__ void cp_async16(uint32_t dst, const void* src) {
    asm volatile("cp.async.cg.shared.global [%0], [%1], 16;"
                 :: "r"(dst), "l"(src));
}
#define CP_COMMIT() asm volatile("cp.async.commit_group;")
#define CP_WAIT0()  asm volatile("cp.async.wait_group 0;")

__device__ __forceinline__ void mma16816(float* d, const unsigned* a,
                                         const unsigned* b) {
    asm volatile(
        "mma.sync.aligned.m16n8k16.row.col.f32.f16.f16.f32 "
        "{%0,%1,%2,%3}, {%4,%5,%6,%7}, {%8,%9}, {%0,%1,%2,%3};"
        : "+f"(d[0]), "+f"(d[1]), "+f"(d[2]), "+f"(d[3])
        : "r"(a[0]), "r"(a[1]), "r"(a[2]), "r"(a[3]), "r"(b[0]), "r"(b[1]));
}
// fp16-accumulator variant (correction passes only)
__device__ __forceinline__ void mma16816h(unsigned* d, const unsigned* a,
                                          const unsigned* b) {
    asm volatile(
        "mma.sync.aligned.m16n8k16.row.col.f16.f16.f16.f16 "
        "{%0,%1}, {%2,%3,%4,%5}, {%6,%7}, {%0,%1};"
        : "+r"(d[0]), "+r"(d[1])
        : "r"(a[0]), "r"(a[1]), "r"(a[2]), "r"(a[3]), "r"(b[0]), "r"(b[1]));
}
__device__ __forceinline__ void ldsm4(unsigned* r, uint32_t addr) {
    asm volatile(
        "ldmatrix.sync.aligned.m8n8.x4.shared.b16 {%0,%1,%2,%3}, [%4];"
        : "=r"(r[0]), "=r"(r[1]), "=r"(r[2]), "=r"(r[3]) : "r"(addr));
}

// ---------------- prep: coalesced tile-transpose split ----------------
extern "C" __global__ void __launch_bounds__(256)
prep_weights(const float* __restrict__ rpw, const float* __restrict__ gw1)
{
    __shared__ float t[32][33];
    const int bid = blockIdx.x;
    const int nt = bid % 6, ktile = bid / 6;
    const int n0 = nt * 32, k0 = ktile * 32;
    const int tid = threadIdx.x;

    const float* src;
    int stride, col0;
    if (n0 < 64) { src = rpw; stride = 64;  col0 = n0; }
    else         { src = gw1; stride = 128; col0 = n0 - 64; }
    #pragma unroll
    for (int p = 0; p < 4; p++) {
        int idx = tid + 256 * p;
        int r = idx >> 5, c = idx & 31;
        t[r][c] = src[(size_t)(k0 + r) * stride + col0 + c];
    }
    __syncthreads();
    #pragma unroll
    for (int p = 0; p < 2; p++) {
        int idx = tid + 256 * p;
        int nl = idx >> 4;
        int kl = (idx & 15) * 2;
        float v0 = t[kl][nl], v1 = t[kl + 1][nl];
        __half2 hi = __floats2half2_rn(v0, v1);
        float2 hf = __half22float2(hi);
        __half2 lo = __floats2half2_rn((v0 - hf.x) * 2048.f, (v1 - hf.y) * 2048.f);
        size_t off = (size_t)(n0 + nl) * D_DIM + k0 + kl;
        *(__half2*)(g_whi + off) = hi;
        *(__half2*)(g_wlo + off) = lo;
    }
}

// ---------------- fused GEMM (mma.sync + ldmatrix) + gate epilogue ----------------
extern "C" __global__ void __launch_bounds__(256, 1)
gemm_gate_mma(const float* __restrict__ h, const float* __restrict__ conflict,
              const float* __restrict__ rpb, const float* __restrict__ rhw,
              const float* __restrict__ rhb, const float* __restrict__ gw1,
              const float* __restrict__ gb1, const float* __restrict__ gw2,
              const float* __restrict__ gb2)
{
    extern __shared__ __half sm[];
    const int tid = threadIdx.x;
    const int wid = tid >> 5, lane = tid & 31;
    const int gid = lane >> 2, tig = lane & 3;
    const int warp_m = wid & 1, warp_n = wid >> 1;
    const int m0 = blockIdx.x * BM;
    const uint32_t sbase = smem_u32(sm);

    float accH[2][6][4];
    unsigned accL[2][6][2];              // fp16x2 accumulators (correction)
    #pragma unroll
    for (int i = 0; i < 2; i++)
        #pragma unroll
        for (int j = 0; j < 6; j++) {
            #pragma unroll
            for (int q = 0; q < 4; q++) accH[i][j][q] = 0.f;
            accL[i][j][0] = 0u; accL[i][j][1] = 0u;
        }

    // ---- ldmatrix per-lane base addresses (bytes), buf 0 ----
    uint32_t adrAH[2], adrAL[2];
    {
        const int row = warp_m * 32 + (lane & 15);
        const int kh = (lane >> 4) * 8;
        #pragma unroll
        for (int i = 0; i < 2; i++) {
            int hoff = (row + i * 16) * ASTR + kh;
            adrAH[i] = sbase + 2u * (OFF_AH + hoff);
            adrAL[i] = sbase + 2u * (OFF_AL + hoff);
        }
    }
    uint32_t adrBH[3], adrBL[3];
    {
        const int nb = warp_n * 48 + ((lane >> 4) & 1) * 8 + (lane & 7);
        const int kh = ((lane >> 3) & 1) * 8;
        #pragma unroll
        for (int p = 0; p < 3; p++) {
            int hoff = (nb + p * 16) * ASTR + kh;
            adrBH[p] = sbase + 2u * (OFF_BH + hoff);
            adrBL[p] = sbase + 2u * (OFF_BL + hoff);
        }
    }

    // ---- A prefetch plumbing ----
    const int aRow0 = tid >> 4;
    const int aChk  = tid & 15;
    const float* aBase = h + (size_t)(m0 + aRow0) * D_DIM + aChk * 4;
    const int aSmem0 = aRow0 * ASTR + aChk * 4;

    // ---- B cp.async plumbing ----
    int bN[6];
    #pragma unroll
    for (int i = 0; i < 6; i++) bN[i] = (tid + 256 * i) >> 3;
    const int bKc = (tid & 7) * 8;

    float4 aReg[4];
    // ---- prologue: tile 0 ----
    #pragma unroll
    for (int i = 0; i < 4; i++)
        aReg[i] = *(const float4*)(aBase + (size_t)i * 16 * D_DIM);
    #pragma unroll
    for (int i = 0; i < 6; i++) {
        const __half* srcH = g_whi + (size_t)bN[i] * D_DIM + bKc;
        const __half* srcL = g_wlo + (size_t)bN[i] * D_DIM + bKc;
        uint32_t d = bN[i] * ASTR + bKc;
        cp_async16(sbase + 2u * (OFF_BH + d), srcH);
        cp_async16(sbase + 2u * (OFF_BL + d), srcL);
    }
    CP_COMMIT();
    #pragma unroll
    for (int i = 0; i < 4; i++) {
        float4 v = aReg[i];
        __half2 h0 = __floats2half2_rn(v.x, v.y);
        __half2 h1 = __floats2half2_rn(v.z, v.w);
        float2 f0 = __half22float2(h0);
        float2 f1 = __half22float2(h1);
        __half2 l0 = __floats2half2_rn((v.x - f0.x) * 2048.f, (v.y - f0.y) * 2048.f);
        __half2 l1 = __floats2half2_rn((v.z - f1.x) * 2048.f, (v.w - f1.y) * 2048.f);
        int off = aSmem0 + i * 16 * ASTR;
        uint2 ph; ph.x = *(unsigned*)&h0; ph.y = *(unsigned*)&h1;
        uint2 pl; pl.x = *(unsigned*)&l0; pl.y = *(unsigned*)&l1;
        *(uint2*)(sm + OFF_AH + off) = ph;
        *(uint2*)(sm + OFF_AL + off) = pl;
    }
    CP_WAIT0();
    __syncthreads();

    for (int kt = 0; kt < NT; kt++) {
        const int buf = kt & 1, nbuf = buf ^ 1;
        if (kt + 1 < NT) {
            const int ko = (kt + 1) * KT;
            #pragma unroll
            for (int i = 0; i < 4; i++)
                aReg[i] = *(const float4*)(aBase + (size_t)i * 16 * D_DIM + ko);
            #pragma unroll
            for (int i = 0; i < 6; i++) {
                const __half* srcH = g_whi + (size_t)bN[i] * D_DIM + ko + bKc;
                const __half* srcL = g_wlo + (size_t)bN[i] * D_DIM + ko + bKc;
                uint32_t d = nbuf * SZ_B + bN[i] * ASTR + bKc;
                cp_async16(sbase + 2u * (OFF_BH + d), srcH);
                cp_async16(sbase + 2u * (OFF_BL + d), srcL);
            }
            CP_COMMIT();
        }

        // ---- compute on buf ----
        const uint32_t abufo = buf * (2u * SZ_A);
        const uint32_t bbufo = buf * (2u * SZ_B);
        #pragma unroll
        for (int ks = 0; ks < 4; ks++) {
            const uint32_t kso = ks * 32;
            unsigned ah[2][4], al[2][4], bh[3][4], bl[3][4];
            #pragma unroll
            for (int i = 0; i < 2; i++) {
                ldsm4(ah[i], adrAH[i] + abufo + kso);
                ldsm4(al[i], adrAL[i] + abufo + kso);
            }
            #pragma unroll
            for (int p = 0; p < 3; p++) {
                ldsm4(bh[p], adrBH[p] + bbufo + kso);
                ldsm4(bl[p], adrBL[p] + bbufo + kso);
            }
            // hh pass (fp32 acc)
            #pragma unroll
            for (int i = 0; i < 2; i++)
                #pragma unroll
                for (int j = 0; j < 6; j++)
                    mma16816(accH[i][j], ah[i], bh[j >> 1] + (j & 1) * 2);
            // lh pass (fp16 acc)
            #pragma unroll
            for (int i = 0; i < 2; i++)
                #pragma unroll
                for (int j = 0; j < 6; j++)
                    mma16816h(accL[i][j], al[i], bh[j >> 1] + (j & 1) * 2);
            // hl pass (fp16 acc)
            #pragma unroll
            for (int i = 0; i < 2; i++)
                #pragma unroll
                for (int j = 0; j < 6; j++)
                    mma16816h(accL[i][j], ah[i], bl[j >> 1] + (j & 1) * 2);
        }

        if (kt + 1 < NT) {
            #pragma unroll
            for (int i = 0; i < 4; i++) {
                float4 v = aReg[i];
                __half2 h0 = __floats2half2_rn(v.x, v.y);
                __half2 h1 = __floats2half2_rn(v.z, v.w);
                float2 f0 = __half22float2(h0);
                float2 f1 = __half22float2(h1);
                __half2 l0 = __floats2half2_rn((v.x - f0.x) * 2048.f, (v.y - f0.y) * 2048.f);
                __half2 l1 = __floats2half2_rn((v.z - f1.x) * 2048.f, (v.w - f1.y) * 2048.f);
                int off = nbuf * SZ_A + aSmem0 + i * 16 * ASTR;
                uint2 ph; ph.x = *(unsigned*)&h0; ph.y = *(unsigned*)&h1;
                uint2 pl; pl.x = *(unsigned*)&l0; pl.y = *(unsigned*)&l1;
                *(uint2*)(sm + OFF_AH + off) = ph;
                *(uint2*)(sm + OFF_AL + off) = pl;
            }
            CP_WAIT0();
        }
        __syncthreads();
    }

    // ---- spill C to smem transposed: CsT[n][m], stride 65 ----
    float* CsT = (float*)sm;
    #pragma unroll
    for (int i = 0; i < 2; i++) {
        const int mr = warp_m * 32 + i * 16 + gid;
        #pragma unroll
        for (int j = 0; j < 6; j++) {
            const int n0 = warp_n * 48 + j * 8 + tig * 2;
            float2 c01 = __half22float2(*(__half2*)&accL[i][j][0]);
            float2 c23 = __half22float2(*(__half2*)&accL[i][j][1]);
            float v0 = accH[i][j][0] + c01.x * (1.f / 2048.f);
            float v1 = accH[i][j][1] + c01.y * (1.f / 2048.f);
            float v2 = accH[i][j][2] + c23.x * (1.f / 2048.f);
            float v3 = accH[i][j][3] + c23.y * (1.f / 2048.f);
            CsT[n0 * 65 + mr]           = v0;
            CsT[(n0 + 1) * 65 + mr]     = v1;
            CsT[n0 * 65 + mr + 8]       = v2;
            CsT[(n0 + 1) * 65 + mr + 8] = v3;
        }
    }
    __syncthreads();

    // ---- per-token gate epilogue ----
    if (tid < BM) {
        const int tok = m0 + tid;
        float rel[4];
        #pragma unroll
        for (int a = 0; a < 4; a++) rel[a] = rhb[a];
        for (int f = 0; f < 64; f++) {
            float fv = fmaxf(CsT[f * 65 + tid] + rpb[f], 0.f);
            #pragma unroll
            for (int a = 0; a < 4; a++) rel[a] += fv * rhw[f * 4 + a];
        }
        #pragma unroll
        for (int a = 0; a < 4; a++) rel[a] = 1.f / (1.f + expf(-rel[a]));

        float conf[4];
        #pragma unroll
        for (int a = 0; a < 4; a++) conf[a] = conflict[(size_t)tok * 4 + a];

        float logits[6];
        #pragma unroll
        for (int c = 0; c < 6; c++) logits[c] = gb2[c];
        for (int j = 0; j < 128; j++) {
            float hv = CsT[(64 + j) * 65 + tid] + gb1[j];
            #pragma unroll
            for (int a = 0; a < 4; a++) {
                hv += rel[a]  * gw1[(size_t)(4096 + a) * 128 + j];
                hv += conf[a] * gw1[(size_t)(4100 + a) * 128 + j];
            }
            hv = fmaxf(hv, 0.f);
            #pragma unroll
            for (int c = 0; c < 6; c++) logits[c] += hv * gw2[j * 6 + c];
        }
        float al4[4] = {logits[2], logits[3], logits[4], logits[5]};
        int ia = 0; float va = al4[0];
        #pragma unroll
        for (int a = 1; a < 4; a++) if (al4[a] > va) { va = al4[a]; ia = a; }
        int ib = (ia == 0) ? 1 : 0; float vb = al4[ib];
        #pragma unroll
        for (int a = 0; a < 4; a++)
            if (a != ia && al4[a] > vb) { vb = al4[a]; ib = a; }

        float mx = fmaxf(fmaxf(logits[0], logits[1]), va);
        float e0 = expf(logits[0] - mx), e1 = expf(logits[1] - mx);
        float ea = expf(va - mx),        eb = expf(vb - mx);
        float inv = 1.f / (e0 + e1 + ea + eb);
        float4 g;
        g.x = e1 * inv;
        g.y = ea * inv;
        g.z = eb * inv;
        g.w = __int_as_float(ia | (ib << 8));
        g_gates[tok] = g;
    }
}

// ---------------- combine: out = g1*sd + ga*res[ia] + gb*res[ib] ----------------
extern "C" __global__ void __launch_bounds__(256)
combine_kernel(const float* __restrict__ sd, const float* __restrict__ ares,
               float* __restrict__ out)
{
    const int tok = blockIdx.x;
    const float4 g = g_gates[tok];
    const int pk = __float_as_int(g.w);
    const int ia = pk & 0xff, ib = (pk >> 8) & 0xff;

    const float4* s4 = (const float4*)(sd + (size_t)tok * D_DIM);
    const float4* a4 = (const float4*)(ares + ((size_t)ia * T_TOKENS + tok) * D_DIM);
    const float4* b4 = (const float4*)(ares + ((size_t)ib * T_TOKENS + tok) * D_DIM);
    float4* o4 = (float4*)(out + (size_t)tok * D_DIM);

    #pragma unroll
    for (int i = 0; i < 4; i++) {
        const int idx = threadIdx.x + 256 * i;
        float4 s = s4[idx], a = a4[idx], b = b4[idx];
        float4 o;
        o.x = g.x * s.x + g.y * a.x + g.z * b.x;
        o.y = g.x * s.y + g.y * a.y + g.z * b.y;
        o.z = g.x * s.z + g.y * a.z + g.z * b.z;
        o.w = g.x * s.w + g.y * a.w + g.z * b.w;
        o4[idx] = o;
    }
}

extern "C" void kernel_launch(void* const* d_in, const int* in_sizes, int n_in,
                              void* d_out, int out_size)
{
    const float* h   = (const float*)d_in[0];
    const float* sd  = (const float*)d_in[1];
    const float* ar  = (const float*)d_in[2];
    const float* cs  = (const float*)d_in[3];
    const float* rpw = (const float*)d_in[4];
    const float* rpb = (const float*)d_in[5];
    const float* rhw = (const float*)d_in[6];
    const float* rhb = (const float*)d_in[7];
    const float* gw1 = (const float*)d_in[8];
    const float* gb1 = (const float*)d_in[9];
    const float* gw2 = (const float*)d_in[10];
    const float* gb2 = (const float*)d_in[11];
    float* out = (float*)d_out;

    static bool attr_set = false;
    if (!attr_set) {
        cudaFuncSetAttribute(gemm_gate_mma,
                             cudaFuncAttributeMaxDynamicSharedMemorySize, SM_BYTES);
        attr_set = true;
    }

    prep_weights<<<768, 256>>>(rpw, gw1);
    gemm_gate_mma<<<T_TOKENS / BM, 256, SM_BYTES>>>(
        h, cs, rpb, rhw, rhb, gw1, gb1, gw2, gb2);
    combine_kernel<<<T_TOKENS, 256>>>(sd, ar, out);
}

// round 13
// speedup vs baseline: 1.0274x; 1.0274x over previous
#include <cuda_runtime.h>
#include <cuda_fp16.h>
#include <cstdint>
#include <math.h>

#define T_TOKENS 8192
#define D_DIM    4096
#define NCOLS    192
#define BM       64
#define KT       64
#define NT       (D_DIM / KT)     // 64
#define ASTR     72               // halves per smem row (64 data + 8 pad)

// smem layout in HALVES
#define SZ_A    (BM * ASTR)            // 4608
#define SZ_B    (NCOLS * ASTR)         // 13824
#define OFF_AH  0
#define OFF_AL  (OFF_AH + 2 * SZ_A)    // 9216
#define OFF_BH  (OFF_AL + 2 * SZ_A)    // 18432
#define OFF_BL  (OFF_BH + 2 * SZ_B)    // 46080
#define SM_HALVES (OFF_BL + 2 * SZ_B)  // 73728
#define SM_BYTES  (SM_HALVES * 2)      // 147456

__device__ float4 g_gates[T_TOKENS];
__device__ __half g_whi[NCOLS * D_DIM];   // weights hi, [n][k]
__device__ __half g_wlo[NCOLS * D_DIM];   // weights (lo*2048), [n][k]

// ---------------- helpers ----------------
__device__ __forceinline__ uint32_t smem_u32(const void* p) {
    uint32_t a;
    asm("{ .reg .u64 t; cvta.to.shared.u64 t, %1; cvt.u32.u64 %0, t; }"
        : "=r"(a) : "l"(p));
    return a;
}
__device__ __forceinline__ void cp_async16(uint32_t dst, const void* src) {
    asm volatile("cp.async.cg.shared.global [%0], [%1], 16;"
                 :: "r"(dst), "l"(src));
}
#define CP_COMMIT() asm volatile("cp.async.commit_group;")
#define CP_WAIT0()  asm volatile("cp.async.wait_group 0;")

__device__ __forceinline__ void mma16816(float* d, const unsigned* a,
                                         const unsigned* b) {
    asm volatile(
        "mma.sync.aligned.m16n8k16.row.col.f32.f16.f16.f32 "
        "{%0,%1,%2,%3}, {%4,%5,%6,%7}, {%8,%9}, {%0,%1,%2,%3};"
        : "+f"(d[0]), "+f"(d[1]), "+f"(d[2]), "+f"(d[3])
        : "r"(a[0]), "r"(a[1]), "r"(a[2]), "r"(a[3]), "r"(b[0]), "r"(b[1]));
}
__device__ __forceinline__ void ldsm4(unsigned* r, uint32_t addr) {
    asm volatile(
        "ldmatrix.sync.aligned.m8n8.x4.shared.b16 {%0,%1,%2,%3}, [%4];"
        : "=r"(r[0]), "=r"(r[1]), "=r"(r[2]), "=r"(r[3]) : "r"(addr));
}

// ---------------- prep: coalesced tile-transpose split ----------------
// grid: 6 n-tiles (of 32 within 192) x 128 k-tiles (of 32) = 768 blocks
extern "C" __global__ void __launch_bounds__(256)
prep_weights(const float* __restrict__ rpw, const float* __restrict__ gw1)
{
    __shared__ float t[32][33];
    const int bid = blockIdx.x;
    const int nt = bid % 6, ktile = bid / 6;
    const int n0 = nt * 32, k0 = ktile * 32;
    const int tid = threadIdx.x;

    const float* src;
    int stride, col0;
    if (n0 < 64) { src = rpw; stride = 64;  col0 = n0; }
    else         { src = gw1; stride = 128; col0 = n0 - 64; }
    #pragma unroll
    for (int p = 0; p < 4; p++) {
        int idx = tid + 256 * p;
        int r = idx >> 5, c = idx & 31;
        t[r][c] = src[(size_t)(k0 + r) * stride + col0 + c];
    }
    __syncthreads();
    #pragma unroll
    for (int p = 0; p < 2; p++) {
        int idx = tid + 256 * p;
        int nl = idx >> 4;            // 0..31
        int kl = (idx & 15) * 2;      // 0..30 even
        float v0 = t[kl][nl], v1 = t[kl + 1][nl];
        __half2 hi = __floats2half2_rn(v0, v1);
        float2 hf = __half22float2(hi);
        __half2 lo = __floats2half2_rn((v0 - hf.x) * 2048.f, (v1 - hf.y) * 2048.f);
        size_t off = (size_t)(n0 + nl) * D_DIM + k0 + kl;
        *(__half2*)(g_whi + off) = hi;
        *(__half2*)(g_wlo + off) = lo;
    }
}

// ---------------- fused GEMM (mma.sync + ldmatrix) + gate epilogue ----------------
extern "C" __global__ void __launch_bounds__(256, 1)
gemm_gate_mma(const float* __restrict__ h, const float* __restrict__ conflict,
              const float* __restrict__ rpb, const float* __restrict__ rhw,
              const float* __restrict__ rhb, const float* __restrict__ gw1,
              const float* __restrict__ gb1, const float* __restrict__ gw2,
              const float* __restrict__ gb2)
{
    extern __shared__ __half sm[];
    const int tid = threadIdx.x;
    const int wid = tid >> 5, lane = tid & 31;
    const int gid = lane >> 2, tig = lane & 3;
    const int warp_m = wid & 1, warp_n = wid >> 1;
    const int m0 = blockIdx.x * BM;
    const uint32_t sbase = smem_u32(sm);

    float accH[2][6][4], accL[2][6][4];
    #pragma unroll
    for (int i = 0; i < 2; i++)
        #pragma unroll
        for (int j = 0; j < 6; j++)
            #pragma unroll
            for (int q = 0; q < 4; q++) { accH[i][j][q] = 0.f; accL[i][j][q] = 0.f; }

    // ---- ldmatrix per-lane base addresses (bytes), buf 0 ----
    uint32_t adrAH[2], adrAL[2];
    {
        const int row = warp_m * 32 + (lane & 15);
        const int kh = (lane >> 4) * 8;
        #pragma unroll
        for (int i = 0; i < 2; i++) {
            int hoff = (row + i * 16) * ASTR + kh;
            adrAH[i] = sbase + 2u * (OFF_AH + hoff);
            adrAL[i] = sbase + 2u * (OFF_AL + hoff);
        }
    }
    uint32_t adrBH[3], adrBL[3];
    {
        const int nb = warp_n * 48 + ((lane >> 4) & 1) * 8 + (lane & 7);
        const int kh = ((lane >> 3) & 1) * 8;
        #pragma unroll
        for (int p = 0; p < 3; p++) {
            int hoff = (nb + p * 16) * ASTR + kh;
            adrBH[p] = sbase + 2u * (OFF_BH + hoff);
            adrBL[p] = sbase + 2u * (OFF_BL + hoff);
        }
    }

    // ---- A prefetch plumbing ----
    const int aRow0 = tid >> 4;
    const int aChk  = tid & 15;
    const float* aBase = h + (size_t)(m0 + aRow0) * D_DIM + aChk * 4;
    const int aSmem0 = aRow0 * ASTR + aChk * 4;

    // ---- B cp.async plumbing ----
    int bN[6];
    #pragma unroll
    for (int i = 0; i < 6; i++) bN[i] = (tid + 256 * i) >> 3;
    const int bKc = (tid & 7) * 8;

    float4 aReg[4];
    // ---- prologue: tile 0 ----
    #pragma unroll
    for (int i = 0; i < 4; i++)
        aReg[i] = *(const float4*)(aBase + (size_t)i * 16 * D_DIM);
    #pragma unroll
    for (int i = 0; i < 6; i++) {
        const __half* srcH = g_whi + (size_t)bN[i] * D_DIM + bKc;
        const __half* srcL = g_wlo + (size_t)bN[i] * D_DIM + bKc;
        uint32_t d = bN[i] * ASTR + bKc;
        cp_async16(sbase + 2u * (OFF_BH + d), srcH);
        cp_async16(sbase + 2u * (OFF_BL + d), srcL);
    }
    CP_COMMIT();
    #pragma unroll
    for (int i = 0; i < 4; i++) {
        float4 v = aReg[i];
        __half2 h0 = __floats2half2_rn(v.x, v.y);
        __half2 h1 = __floats2half2_rn(v.z, v.w);
        float2 f0 = __half22float2(h0);
        float2 f1 = __half22float2(h1);
        __half2 l0 = __floats2half2_rn((v.x - f0.x) * 2048.f, (v.y - f0.y) * 2048.f);
        __half2 l1 = __floats2half2_rn((v.z - f1.x) * 2048.f, (v.w - f1.y) * 2048.f);
        int off = aSmem0 + i * 16 * ASTR;
        uint2 ph; ph.x = *(unsigned*)&h0; ph.y = *(unsigned*)&h1;
        uint2 pl; pl.x = *(unsigned*)&l0; pl.y = *(unsigned*)&l1;
        *(uint2*)(sm + OFF_AH + off) = ph;
        *(uint2*)(sm + OFF_AL + off) = pl;
    }
    CP_WAIT0();
    __syncthreads();

    for (int kt = 0; kt < NT; kt++) {
        const int buf = kt & 1, nbuf = buf ^ 1;
        if (kt + 1 < NT) {
            const int ko = (kt + 1) * KT;
            #pragma unroll
            for (int i = 0; i < 4; i++)
                aReg[i] = *(const float4*)(aBase + (size_t)i * 16 * D_DIM + ko);
            #pragma unroll
            for (int i = 0; i < 6; i++) {
                const __half* srcH = g_whi + (size_t)bN[i] * D_DIM + ko + bKc;
                const __half* srcL = g_wlo + (size_t)bN[i] * D_DIM + ko + bKc;
                uint32_t d = nbuf * SZ_B + bN[i] * ASTR + bKc;
                cp_async16(sbase + 2u * (OFF_BH + d), srcH);
                cp_async16(sbase + 2u * (OFF_BL + d), srcL);
            }
            CP_COMMIT();
        }

        // ---- compute on buf ----
        const uint32_t abufo = buf * (2u * SZ_A);
        const uint32_t bbufo = buf * (2u * SZ_B);
        #pragma unroll
        for (int ks = 0; ks < 4; ks++) {
            const uint32_t kso = ks * 32;
            unsigned ah[2][4], al[2][4], bh[3][4], bl[3][4];
            #pragma unroll
            for (int i = 0; i < 2; i++) {
                ldsm4(ah[i], adrAH[i] + abufo + kso);
                ldsm4(al[i], adrAL[i] + abufo + kso);
            }
            #pragma unroll
            for (int p = 0; p < 3; p++) {
                ldsm4(bh[p], adrBH[p] + bbufo + kso);
                ldsm4(bl[p], adrBL[p] + bbufo + kso);
            }
            #pragma unroll
            for (int i = 0; i < 2; i++)
                #pragma unroll
                for (int j = 0; j < 6; j++)
                    mma16816(accH[i][j], ah[i], bh[j >> 1] + (j & 1) * 2);
            #pragma unroll
            for (int i = 0; i < 2; i++)
                #pragma unroll
                for (int j = 0; j < 6; j++)
                    mma16816(accL[i][j], al[i], bh[j >> 1] + (j & 1) * 2);
            #pragma unroll
            for (int i = 0; i < 2; i++)
                #pragma unroll
                for (int j = 0; j < 6; j++)
                    mma16816(accL[i][j], ah[i], bl[j >> 1] + (j & 1) * 2);
        }

        if (kt + 1 < NT) {
            #pragma unroll
            for (int i = 0; i < 4; i++) {
                float4 v = aReg[i];
                __half2 h0 = __floats2half2_rn(v.x, v.y);
                __half2 h1 = __floats2half2_rn(v.z, v.w);
                float2 f0 = __half22float2(h0);
                float2 f1 = __half22float2(h1);
                __half2 l0 = __floats2half2_rn((v.x - f0.x) * 2048.f, (v.y - f0.y) * 2048.f);
                __half2 l1 = __floats2half2_rn((v.z - f1.x) * 2048.f, (v.w - f1.y) * 2048.f);
                int off = nbuf * SZ_A + aSmem0 + i * 16 * ASTR;
                uint2 ph; ph.x = *(unsigned*)&h0; ph.y = *(unsigned*)&h1;
                uint2 pl; pl.x = *(unsigned*)&l0; pl.y = *(unsigned*)&l1;
                *(uint2*)(sm + OFF_AH + off) = ph;
                *(uint2*)(sm + OFF_AL + off) = pl;
            }
            CP_WAIT0();
        }
        __syncthreads();
    }

    // ---- spill C to smem transposed: CsT[n][m], stride 65 ----
    float* CsT = (float*)sm;
    #pragma unroll
    for (int i = 0; i < 2; i++) {
        const int mr = warp_m * 32 + i * 16 + gid;
        #pragma unroll
        for (int j = 0; j < 6; j++) {
            const int n0 = warp_n * 48 + j * 8 + tig * 2;
            float v0 = accH[i][j][0] + accL[i][j][0] * (1.f / 2048.f);
            float v1 = accH[i][j][1] + accL[i][j][1] * (1.f / 2048.f);
            float v2 = accH[i][j][2] + accL[i][j][2] * (1.f / 2048.f);
            float v3 = accH[i][j][3] + accL[i][j][3] * (1.f / 2048.f);
            CsT[n0 * 65 + mr]           = v0;
            CsT[(n0 + 1) * 65 + mr]     = v1;
            CsT[n0 * 65 + mr + 8]       = v2;
            CsT[(n0 + 1) * 65 + mr + 8] = v3;
        }
    }
    __syncthreads();

    // ---- per-token gate epilogue ----
    if (tid < BM) {
        const int tok = m0 + tid;
        float rel[4];
        #pragma unroll
        for (int a = 0; a < 4; a++) rel[a] = rhb[a];
        for (int f = 0; f < 64; f++) {
            float fv = fmaxf(CsT[f * 65 + tid] + rpb[f], 0.f);
            #pragma unroll
            for (int a = 0; a < 4; a++) rel[a] += fv * rhw[f * 4 + a];
        }
        #pragma unroll
        for (int a = 0; a < 4; a++) rel[a] = 1.f / (1.f + expf(-rel[a]));

        float conf[4];
        #pragma unroll
        for (int a = 0; a < 4; a++) conf[a] = conflict[(size_t)tok * 4 + a];

        float logits[6];
        #pragma unroll
        for (int c = 0; c < 6; c++) logits[c] = gb2[c];
        for (int j = 0; j < 128; j++) {
            float hv = CsT[(64 + j) * 65 + tid] + gb1[j];
            #pragma unroll
            for (int a = 0; a < 4; a++) {
                hv += rel[a]  * gw1[(size_t)(4096 + a) * 128 + j];
                hv += conf[a] * gw1[(size_t)(4100 + a) * 128 + j];
            }
            hv = fmaxf(hv, 0.f);
            #pragma unroll
            for (int c = 0; c < 6; c++) logits[c] += hv * gw2[j * 6 + c];
        }
        float al4[4] = {logits[2], logits[3], logits[4], logits[5]};
        int ia = 0; float va = al4[0];
        #pragma unroll
        for (int a = 1; a < 4; a++) if (al4[a] > va) { va = al4[a]; ia = a; }
        int ib = (ia == 0) ? 1 : 0; float vb = al4[ib];
        #pragma unroll
        for (int a = 0; a < 4; a++)
            if (a != ia && al4[a] > vb) { vb = al4[a]; ib = a; }

        float mx = fmaxf(fmaxf(logits[0], logits[1]), va);
        float e0 = expf(logits[0] - mx), e1 = expf(logits[1] - mx);
        float ea = expf(va - mx),        eb = expf(vb - mx);
        float inv = 1.f / (e0 + e1 + ea + eb);
        float4 g;
        g.x = e1 * inv;
        g.y = ea * inv;
        g.z = eb * inv;
        g.w = __int_as_float(ia | (ib << 8));
        g_gates[tok] = g;
    }
}

// ---------------- combine: out = g1*sd + ga*res[ia] + gb*res[ib] ----------------
extern "C" __global__ void __launch_bounds__(256)
combine_kernel(const float* __restrict__ sd, const float* __restrict__ ares,
               float* __restrict__ out)
{
    const int tok = blockIdx.x;
    const float4 g = g_gates[tok];
    const int pk = __float_as_int(g.w);
    const int ia = pk & 0xff, ib = (pk >> 8) & 0xff;

    const float4* s4 = (const float4*)(sd + (size_t)tok * D_DIM);
    const float4* a4 = (const float4*)(ares + ((size_t)ia * T_TOKENS + tok) * D_DIM);
    const float4* b4 = (const float4*)(ares + ((size_t)ib * T_TOKENS + tok) * D_DIM);
    float4* o4 = (float4*)(out + (size_t)tok * D_DIM);

    #pragma unroll
    for (int i = 0; i < 4; i++) {
        const int idx = threadIdx.x + 256 * i;
        float4 s = s4[idx], a = a4[idx], b = b4[idx];
        float4 o;
        o.x = g.x * s.x + g.y * a.x + g.z * b.x;
        o.y = g.x * s.y + g.y * a.y + g.z * b.y;
        o.z = g.x * s.z + g.y * a.z + g.z * b.z;
        o.w = g.x * s.w + g.y * a.w + g.z * b.w;
        o4[idx] = o;
    }
}

extern "C" void kernel_launch(void* const* d_in, const int* in_sizes, int n_in,
                              void* d_out, int out_size)
{
    const float* h   = (const float*)d_in[0];
    const float* sd  = (const float*)d_in[1];
    const float* ar  = (const float*)d_in[2];
    const float* cs  = (const float*)d_in[3];
    const float* rpw = (const float*)d_in[4];
    const float* rpb = (const float*)d_in[5];
    const float* rhw = (const float*)d_in[6];
    const float* rhb = (const float*)d_in[7];
    const float* gw1 = (const float*)d_in[8];
    const float* gb1 = (const float*)d_in[9];
    const float* gw2 = (const float*)d_in[10];
    const float* gb2 = (const float*)d_in[11];
    float* out = (float*)d_out;

    static bool attr_set = false;
    if (!attr_set) {
        cudaFuncSetAttribute(gemm_gate_mma,
                             cudaFuncAttributeMaxDynamicSharedMemorySize, SM_BYTES);
        attr_set = true;
    }

    prep_weights<<<768, 256>>>(rpw, gw1);
    gemm_gate_mma<<<T_TOKENS / BM, 256, SM_BYTES>>>(
        h, cs, rpb, rhw, rhb, gw1, gb1, gw2, gb2);
    combine_kernel<<<T_TOKENS, 256>>>(sd, ar, out);
}